// round 3
// baseline (speedup 1.0000x reference)
#include <cuda_runtime.h>

// Problem constants
#define BH   32      // B*H
#define S    2048
#define D    64
#define TQ   16      // q rows per CTA
#define SCP  2052    // padded score row stride (floats)
#define KSP  65      // K tile row stride (floats), conflict-free scalar reads
#define VSP  68      // V tile row stride (floats), float4-aligned + conflict-free
#define NEG_INF_F  (-1e10f)
#define SCALE      (0.125f)   // 1/sqrt(64)

// shared memory layout (floats)
#define SC_FLOATS  (TQ * SCP)        // 32832
#define KV_FLOATS  (256 * VSP)       // 17408 (K tile uses KSP stride inside same buf)
#define QS_FLOATS  (TQ * D)          // 1024
#define SMEM_FLOATS (SC_FLOATS + KV_FLOATS + QS_FLOATS + TQ + 16)
#define SMEM_BYTES  (SMEM_FLOATS * 4)

__global__ __launch_bounds__(256, 1)
void dist_attn_kernel(const float* __restrict__ Q,
                      const float* __restrict__ K,
                      const float* __restrict__ V,
                      const float* __restrict__ dist,
                      const int* __restrict__ mask,
                      float* __restrict__ ctx,
                      float* __restrict__ attn)
{
    extern __shared__ float sm[];
    float* sc   = sm;                       // [TQ][SCP] unnormalized scores/probs
    float* kv   = sm + SC_FLOATS;           // K/V tile + reduction scratch
    float* Qs   = kv + KV_FLOATS;           // [TQ][D]
    float* invs = Qs + QS_FLOATS;           // [TQ] 1/rowsum

    const int t  = threadIdx.x;
    const int bh = blockIdx.y;
    const int q0 = blockIdx.x * TQ;
    const size_t rowbase = (size_t)bh * S;  // global row index base for this (b,h)

    // ---- load Q tile: 16x64 = 256 float4 ----
    {
        const float4* Qg = (const float4*)(Q + (rowbase + q0) * D);
        ((float4*)Qs)[t] = Qg[t];
    }
    __syncthreads();

    // ================= Phase 1: scores = Q @ K^T =================
    // 8 K-tiles of 256 rows. Each thread owns one k-row per tile.
    for (int p = 0; p < S / 256; ++p) {
        // cooperative load K tile (coalesced float4), store padded
        const float4* Kg = (const float4*)(K + (rowbase + (size_t)p * 256) * D);
        #pragma unroll
        for (int i = 0; i < 16; ++i) {
            int fidx = t + i * 256;
            int kr = fidx >> 4;
            int d4 = fidx & 15;
            float4 v = Kg[fidx];
            float* dst = kv + kr * KSP + d4 * 4;
            dst[0] = v.x; dst[1] = v.y; dst[2] = v.z; dst[3] = v.w;
        }
        __syncthreads();

        float acc[TQ];
        #pragma unroll
        for (int q = 0; q < TQ; ++q) acc[q] = 0.f;

        const float* krow = kv + t * KSP;   // this thread's K row (conflict-free)
        #pragma unroll 4
        for (int d = 0; d < D; d += 4) {
            float k0 = krow[d + 0];
            float k1 = krow[d + 1];
            float k2 = krow[d + 2];
            float k3 = krow[d + 3];
            #pragma unroll
            for (int q = 0; q < TQ; ++q) {
                float4 qv = *(const float4*)(Qs + q * D + d);  // broadcast
                acc[q] = fmaf(qv.x, k0, acc[q]);
                acc[q] = fmaf(qv.y, k1, acc[q]);
                acc[q] = fmaf(qv.z, k2, acc[q]);
                acc[q] = fmaf(qv.w, k3, acc[q]);
            }
        }
        #pragma unroll
        for (int q = 0; q < TQ; ++q)
            sc[q * SCP + p * 256 + t] = acc[q];
        __syncthreads();
    }

    // ================= Phase 2: scale * dist, mask, softmax =================
    // Warp w handles rows 2w and 2w+1. Row values held in 64 registers.
    {
        const int warp = t >> 5, lane = t & 31;
        #pragma unroll
        for (int r = 0; r < 2; ++r) {
            const int q  = warp * 2 + r;
            const size_t grow = rowbase + q0 + q;
            const float* distRow = dist + grow * S;
            const int*   maskRow = mask + grow * S;

            float sv[64];
            float m = -3.4e38f;
            #pragma unroll
            for (int i = 0; i < 64; ++i) {
                int k = i * 32 + lane;
                float s  = sc[q * SCP + k];
                float df = distRow[k];
                s = df * s * SCALE;
                if (maskRow[k]) s = NEG_INF_F;
                sv[i] = s;
                m = fmaxf(m, s);
            }
            #pragma unroll
            for (int o = 16; o > 0; o >>= 1)
                m = fmaxf(m, __shfl_xor_sync(0xffffffffu, m, o));

            float sum = 0.f;
            #pragma unroll
            for (int i = 0; i < 64; ++i) {
                float pv = __expf(sv[i] - m);
                sv[i] = pv;
                sum += pv;
            }
            #pragma unroll
            for (int o = 16; o > 0; o >>= 1)
                sum += __shfl_xor_sync(0xffffffffu, sum, o);
            float inv = 1.f / sum;

            float* attnRow = attn + grow * S;
            #pragma unroll
            for (int i = 0; i < 64; ++i) {
                int k = i * 32 + lane;
                sc[q * SCP + k] = sv[i];          // unnormalized p for GEMM2
                attnRow[k]      = sv[i] * inv;    // normalized output
            }
            if (lane == 0) invs[q] = inv;
        }
    }
    __syncthreads();

    // ================= Phase 3: context = softmax @ V =================
    // thread = (half over k, q, 8 d-columns); split-k reduce via smem.
    {
        const int half  = t >> 7;
        const int qq    = (t >> 3) & 15;
        const int dbase = (t & 7) * 8;

        float a0[8];
        #pragma unroll
        for (int j = 0; j < 8; ++j) a0[j] = 0.f;

        for (int tv = 0; tv < S / 256; ++tv) {
            const float4* Vg = (const float4*)(V + (rowbase + (size_t)tv * 256) * D);
            #pragma unroll
            for (int i = 0; i < 16; ++i) {
                int fidx = t + i * 256;
                int kr = fidx >> 4;
                int d4 = fidx & 15;
                float4 v = Vg[fidx];
                float* dst = kv + kr * VSP + d4 * 4;
                dst[0] = v.x; dst[1] = v.y; dst[2] = v.z; dst[3] = v.w;
            }
            __syncthreads();

            const float* scRow = sc + qq * SCP + tv * 256 + half * 128;
            const float* vb    = kv + half * 128 * VSP + dbase;
            #pragma unroll 8
            for (int kk = 0; kk < 128; ++kk) {
                float a = scRow[kk];
                const float* vr = vb + kk * VSP;
                float4 v0 = *(const float4*)(vr);
                float4 v1 = *(const float4*)(vr + 4);
                a0[0] = fmaf(a, v0.x, a0[0]);
                a0[1] = fmaf(a, v0.y, a0[1]);
                a0[2] = fmaf(a, v0.z, a0[2]);
                a0[3] = fmaf(a, v0.w, a0[3]);
                a0[4] = fmaf(a, v1.x, a0[4]);
                a0[5] = fmaf(a, v1.y, a0[5]);
                a0[6] = fmaf(a, v1.z, a0[6]);
                a0[7] = fmaf(a, v1.w, a0[7]);
            }
            __syncthreads();
        }

        // split-k reduction across the two halves (reuse kv as scratch)
        float* red = kv;
        if (half == 0) {
            #pragma unroll
            for (int j = 0; j < 8; ++j) red[qq * 64 + dbase + j] = a0[j];
        }
        __syncthreads();
        if (half == 1) {
            float inv = invs[qq];
            float* out = ctx + (rowbase + q0 + qq) * D + dbase;
            #pragma unroll
            for (int j = 0; j < 8; ++j)
                out[j] = (red[qq * 64 + dbase + j] + a0[j]) * inv;
        }
    }
}

extern "C" void kernel_launch(void* const* d_in, const int* in_sizes, int n_in,
                              void* d_out, int out_size)
{
    const float* Q    = (const float*)d_in[0];
    const float* K    = (const float*)d_in[1];
    const float* V    = (const float*)d_in[2];
    const float* dist = (const float*)d_in[3];
    const int*   mask = (const int*)d_in[4];

    float* ctx  = (float*)d_out;                       // [B,H,S,D]
    float* attn = (float*)d_out + (size_t)BH * S * D;  // [B,H,S,S]

    cudaFuncSetAttribute(dist_attn_kernel,
                         cudaFuncAttributeMaxDynamicSharedMemorySize,
                         SMEM_BYTES);

    dim3 grid(S / TQ, BH);
    dist_attn_kernel<<<grid, 256, SMEM_BYTES>>>(Q, K, V, dist, mask, ctx, attn);
}

// round 4
// speedup vs baseline: 1.8326x; 1.8326x over previous
#include <cuda_runtime.h>

#define BH   32
#define S    2048
#define D    64
#define TQ   16
#define NT   512
#define SCP  2052          // padded score row stride (floats)
#define KVP  68            // K/V tile row stride (floats)
#define NEG_INF_F (-1e10f)
#define SCALE     (0.125f) // 1/sqrt(64)

#define SC_FLOATS (TQ * SCP)     // 32832
#define KV_FLOATS (256 * KVP)    // 17408
#define QS_FLOATS (TQ * D)       // 1024
#define SMEM_FLOATS (SC_FLOATS + KV_FLOATS + QS_FLOATS + 32)
#define SMEM_BYTES  (SMEM_FLOATS * 4)

__global__ __launch_bounds__(NT, 1)
void dist_attn_kernel(const float* __restrict__ Q,
                      const float* __restrict__ K,
                      const float* __restrict__ V,
                      const float* __restrict__ dist,
                      const int* __restrict__ mask,
                      float* __restrict__ ctx,
                      float* __restrict__ attn)
{
    extern __shared__ float sm[];
    float* sc   = sm;                 // [TQ][SCP] scores -> probs
    float* kv   = sm + SC_FLOATS;     // K/V tile, later split-k scratch
    float* Qs   = kv + KV_FLOATS;     // [TQ][D]
    float* invs = Qs + QS_FLOATS;     // [TQ]

    const int t  = threadIdx.x;
    const int bh = blockIdx.y;
    const int q0 = blockIdx.x * TQ;
    const size_t rowbase = (size_t)bh * S;

    // ---- Q tile: 16x64 = 256 float4 ----
    if (t < 256)
        ((float4*)Qs)[t] = ((const float4*)(Q + (rowbase + q0) * D))[t];
    __syncthreads();

    // ================= Phase 1: scores = Q @ K^T =================
    // thread = [qh(1)][kpair(7)][dh(1)] : 8q x 2k x 32d, shfl-reduce d halves.
    {
        const int dh = t & 1;
        const int kp = (t >> 1) & 127;
        const int qh = t >> 8;
        const int k0 = kp * 2;
        const float* qbase = Qs + qh * 8 * D + dh * 32;

        for (int p = 0; p < S / 256; ++p) {
            const float4* Kg = (const float4*)(K + (rowbase + (size_t)p * 256) * D);
            #pragma unroll
            for (int i = 0; i < 8; ++i) {
                int fidx = t + i * NT;
                int kr = fidx >> 4, d4 = fidx & 15;
                *(float4*)(kv + kr * KVP + d4 * 4) = Kg[fidx];
            }
            __syncthreads();

            float acc[8][2];
            #pragma unroll
            for (int q = 0; q < 8; ++q) { acc[q][0] = 0.f; acc[q][1] = 0.f; }

            const float* ka = kv + k0 * KVP + dh * 32;
            #pragma unroll
            for (int dd = 0; dd < 32; dd += 4) {
                float4 kva = *(const float4*)(ka + dd);
                float4 kvb = *(const float4*)(ka + KVP + dd);
                #pragma unroll
                for (int q = 0; q < 8; ++q) {
                    float4 qv = *(const float4*)(qbase + q * D + dd); // broadcast
                    acc[q][0] = fmaf(qv.x, kva.x, acc[q][0]);
                    acc[q][0] = fmaf(qv.y, kva.y, acc[q][0]);
                    acc[q][0] = fmaf(qv.z, kva.z, acc[q][0]);
                    acc[q][0] = fmaf(qv.w, kva.w, acc[q][0]);
                    acc[q][1] = fmaf(qv.x, kvb.x, acc[q][1]);
                    acc[q][1] = fmaf(qv.y, kvb.y, acc[q][1]);
                    acc[q][1] = fmaf(qv.z, kvb.z, acc[q][1]);
                    acc[q][1] = fmaf(qv.w, kvb.w, acc[q][1]);
                }
            }
            #pragma unroll
            for (int q = 0; q < 8; ++q) {
                float a0 = acc[q][0] + __shfl_xor_sync(0xffffffffu, acc[q][0], 1);
                float a1 = acc[q][1] + __shfl_xor_sync(0xffffffffu, acc[q][1], 1);
                if (dh == 0)
                    *(float2*)(sc + (qh * 8 + q) * SCP + p * 256 + k0) = make_float2(a0, a1);
            }
            __syncthreads();
        }
    }

    // ================= Phase 2: scale, mask, softmax (warp = row) =================
    {
        const int warp = t >> 5, lane = t & 31;
        const int q = warp;
        const size_t grow = rowbase + q0 + q;
        const float4* distRow = (const float4*)(dist + grow * S);
        const int4*   maskRow = (const int4*)(mask + grow * S);
        float4* scRow   = (float4*)(sc + q * SCP);
        float4* attnRow = (float4*)(attn + grow * S);

        float4 sv[16];
        float m = -3.4e38f;
        #pragma unroll
        for (int i = 0; i < 16; ++i) {
            int idx = i * 32 + lane;
            float4 s  = scRow[idx];
            float4 df = distRow[idx];
            int4   mk = maskRow[idx];
            s.x = mk.x ? NEG_INF_F : df.x * s.x * SCALE;
            s.y = mk.y ? NEG_INF_F : df.y * s.y * SCALE;
            s.z = mk.z ? NEG_INF_F : df.z * s.z * SCALE;
            s.w = mk.w ? NEG_INF_F : df.w * s.w * SCALE;
            sv[i] = s;
            m = fmaxf(m, fmaxf(fmaxf(s.x, s.y), fmaxf(s.z, s.w)));
        }
        #pragma unroll
        for (int o = 16; o > 0; o >>= 1)
            m = fmaxf(m, __shfl_xor_sync(0xffffffffu, m, o));

        float sum = 0.f;
        #pragma unroll
        for (int i = 0; i < 16; ++i) {
            float4 s = sv[i];
            s.x = __expf(s.x - m); s.y = __expf(s.y - m);
            s.z = __expf(s.z - m); s.w = __expf(s.w - m);
            sv[i] = s;
            sum += s.x + s.y + s.z + s.w;
        }
        #pragma unroll
        for (int o = 16; o > 0; o >>= 1)
            sum += __shfl_xor_sync(0xffffffffu, sum, o);
        float inv = 1.f / sum;

        #pragma unroll
        for (int i = 0; i < 16; ++i) {
            int idx = i * 32 + lane;
            float4 s = sv[i];
            scRow[idx] = s;                                   // unnormalized p
            attnRow[idx] = make_float4(s.x * inv, s.y * inv,
                                       s.z * inv, s.w * inv); // normalized out
        }
        if (lane == 0) invs[q] = inv;
    }
    __syncthreads();

    // ================= Phase 3: context = p @ V =================
    // thread = [kg(4) = warp][qb(1)][db(4)] : 16-way split-k, 8q x 4d per thread.
    {
        const int db = t & 15;
        const int qb = (t >> 4) & 1;
        const int kg = t >> 5;

        float acc[8][4];
        #pragma unroll
        for (int i = 0; i < 8; ++i)
            #pragma unroll
            for (int j = 0; j < 4; ++j) acc[i][j] = 0.f;

        for (int p = 0; p < S / 256; ++p) {
            const float4* Vg = (const float4*)(V + (rowbase + (size_t)p * 256) * D);
            #pragma unroll
            for (int i = 0; i < 8; ++i) {
                int fidx = t + i * NT;
                int kr = fidx >> 4, d4 = fidx & 15;
                *(float4*)(kv + kr * KVP + d4 * 4) = Vg[fidx];
            }
            __syncthreads();

            const float* scBase = sc + p * 256 + kg * 16;
            #pragma unroll
            for (int step = 0; step < 16; ++step) {
                int krow = kg * 16 + step;
                float4 v = *(const float4*)(kv + krow * KVP + db * 4); // conflict-free
                #pragma unroll
                for (int i = 0; i < 8; ++i) {
                    float pw = scBase[(qb * 8 + i) * SCP + step];      // broadcast
                    acc[i][0] = fmaf(pw, v.x, acc[i][0]);
                    acc[i][1] = fmaf(pw, v.y, acc[i][1]);
                    acc[i][2] = fmaf(pw, v.z, acc[i][2]);
                    acc[i][3] = fmaf(pw, v.w, acc[i][3]);
                }
            }
            __syncthreads();
        }

        // split-k reduce: part[kg][q][d] in kv (16 x 1024 floats)
        #pragma unroll
        for (int i = 0; i < 8; ++i)
            *(float4*)(kv + kg * 1024 + (qb * 8 + i) * 64 + db * 4) =
                make_float4(acc[i][0], acc[i][1], acc[i][2], acc[i][3]);
        __syncthreads();

        #pragma unroll
        for (int o = t; o < TQ * D; o += NT) {
            int q = o >> 6;
            float s = 0.f;
            #pragma unroll
            for (int g = 0; g < 16; ++g) s += kv[g * 1024 + o];
            ctx[(rowbase + q0) * D + o] = s * invs[q];
        }
    }
}

extern "C" void kernel_launch(void* const* d_in, const int* in_sizes, int n_in,
                              void* d_out, int out_size)
{
    const float* Q    = (const float*)d_in[0];
    const float* K    = (const float*)d_in[1];
    const float* V    = (const float*)d_in[2];
    const float* dist = (const float*)d_in[3];
    const int*   mask = (const int*)d_in[4];

    float* ctx  = (float*)d_out;
    float* attn = (float*)d_out + (size_t)BH * S * D;

    cudaFuncSetAttribute(dist_attn_kernel,
                         cudaFuncAttributeMaxDynamicSharedMemorySize,
                         SMEM_BYTES);

    dim3 grid(S / TQ, BH);
    dist_attn_kernel<<<grid, NT, SMEM_BYTES>>>(Q, K, V, dist, mask, ctx, attn);
}

// round 5
// speedup vs baseline: 2.4127x; 1.3165x over previous
#include <cuda_runtime.h>
#include <cstdint>

#define BH   32
#define S    2048
#define D    64
#define TQ   16
#define NT   512
#define SCP  2052          // score row stride (floats), 2052 % 32 == 4
#define KVP  68            // K tile row stride
#define VTP  259           // V^T tile row stride (odd: 259 % 32 == 3)
#define QSP  68            // Q tile row stride
#define RDP  68            // reduction scratch row stride
#define NEG_INF_F (-1e10f)
#define SCALE     (0.125f)

#define SC_FLOATS  (TQ * SCP)        // 32832
#define BUF_FLOATS 17408             // max(256*68, 64*259, 16*16*68)
#define QS_FLOATS  (TQ * QSP)        // 1088
#define SMEM_FLOATS (SC_FLOATS + BUF_FLOATS + QS_FLOATS + 32)
#define SMEM_BYTES  (SMEM_FLOATS * 4)

__device__ __forceinline__ void split_tf32(float a, uint32_t& hi, uint32_t& lo) {
    uint32_t h;
    asm("cvt.rna.tf32.f32 %0, %1;" : "=r"(h) : "f"(a));
    hi = h;
    lo = __float_as_uint(a - __uint_as_float(h));
}

__device__ __forceinline__ void mma_tf32(float* c,
                                         uint32_t a0, uint32_t a1, uint32_t a2, uint32_t a3,
                                         uint32_t b0, uint32_t b1) {
    asm volatile(
        "mma.sync.aligned.m16n8k8.row.col.f32.tf32.tf32.f32 "
        "{%0,%1,%2,%3},{%4,%5,%6,%7},{%8,%9},{%0,%1,%2,%3};"
        : "+f"(c[0]), "+f"(c[1]), "+f"(c[2]), "+f"(c[3])
        : "r"(a0), "r"(a1), "r"(a2), "r"(a3), "r"(b0), "r"(b1));
}

__global__ __launch_bounds__(NT, 1)
void dist_attn_kernel(const float* __restrict__ Q,
                      const float* __restrict__ K,
                      const float* __restrict__ V,
                      const float* __restrict__ dist,
                      const int* __restrict__ mask,
                      float* __restrict__ ctx,
                      float* __restrict__ attn)
{
    extern __shared__ float sm[];
    float* sc   = sm;                 // [TQ][SCP] scores -> probs
    float* buf  = sm + SC_FLOATS;     // K tile / V^T tile / split-k scratch
    float* Qs   = buf + BUF_FLOATS;   // [TQ][QSP]
    float* invs = Qs + QS_FLOATS;     // [TQ]

    const int t    = threadIdx.x;
    const int warp = t >> 5;
    const int lane = t & 31;
    const int gid  = lane >> 2;   // group id (row within fragment)
    const int tig  = lane & 3;    // thread in group (col within fragment)
    const int bh = blockIdx.y;
    const int q0 = blockIdx.x * TQ;
    const size_t rowbase = (size_t)bh * S;

    // ---- Q tile: 16x64, padded stride QSP ----
    if (t < 256) {
        const float4 v = ((const float4*)(Q + (rowbase + q0) * D))[t];
        int qr = t >> 4, d4 = t & 15;
        *(float4*)(Qs + qr * QSP + d4 * 4) = v;
    }
    __syncthreads();

    // ================= Phase 1: scores = Q @ K^T (3xTF32 mma) =================
    {
        // Persistent A fragments for Q: 8 k-steps x 4 regs, hi+lo
        uint32_t ahi[8][4], alo[8][4];
        #pragma unroll
        for (int ks = 0; ks < 8; ++ks) {
            float a0 = Qs[gid * QSP       + ks * 8 + tig];
            float a1 = Qs[(gid + 8) * QSP + ks * 8 + tig];
            float a2 = Qs[gid * QSP       + ks * 8 + tig + 4];
            float a3 = Qs[(gid + 8) * QSP + ks * 8 + tig + 4];
            split_tf32(a0, ahi[ks][0], alo[ks][0]);
            split_tf32(a1, ahi[ks][1], alo[ks][1]);
            split_tf32(a2, ahi[ks][2], alo[ks][2]);
            split_tf32(a3, ahi[ks][3], alo[ks][3]);
        }

        for (int p = 0; p < S / 256; ++p) {
            const float4* Kg = (const float4*)(K + (rowbase + (size_t)p * 256) * D);
            #pragma unroll
            for (int i = 0; i < 8; ++i) {
                int fidx = t + i * NT;
                int kr = fidx >> 4, d4 = fidx & 15;
                *(float4*)(buf + kr * KVP + d4 * 4) = Kg[fidx];
            }
            __syncthreads();

            #pragma unroll
            for (int nt = 0; nt < 2; ++nt) {
                const int nb = (warp * 2 + nt) * 8;
                float acc[4] = {0.f, 0.f, 0.f, 0.f};
                const float* kb = buf + (nb + gid) * KVP + tig;
                #pragma unroll
                for (int ks = 0; ks < 8; ++ks) {
                    float b0f = kb[ks * 8];
                    float b1f = kb[ks * 8 + 4];
                    uint32_t bh0, bl0, bh1, bl1;
                    split_tf32(b0f, bh0, bl0);
                    split_tf32(b1f, bh1, bl1);
                    mma_tf32(acc, ahi[ks][0], ahi[ks][1], ahi[ks][2], ahi[ks][3], bh0, bh1);
                    mma_tf32(acc, ahi[ks][0], ahi[ks][1], ahi[ks][2], ahi[ks][3], bl0, bl1);
                    mma_tf32(acc, alo[ks][0], alo[ks][1], alo[ks][2], alo[ks][3], bh0, bh1);
                }
                const int col = p * 256 + nb + 2 * tig;
                *(float2*)(sc + gid * SCP + col)       = make_float2(acc[0], acc[1]);
                *(float2*)(sc + (gid + 8) * SCP + col) = make_float2(acc[2], acc[3]);
            }
            __syncthreads();
        }
    }

    // ================= Phase 2: scale, mask, softmax (warp = row) =================
    {
        const int q = warp;
        const size_t grow = rowbase + q0 + q;
        const float4* distRow = (const float4*)(dist + grow * S);
        const int4*   maskRow = (const int4*)(mask + grow * S);
        float4* scRow   = (float4*)(sc + q * SCP);
        float4* attnRow = (float4*)(attn + grow * S);

        float4 sv[16];
        float m = -3.4e38f;
        #pragma unroll
        for (int i = 0; i < 16; ++i) {
            int idx = i * 32 + lane;
            float4 s  = scRow[idx];
            float4 df = distRow[idx];
            int4   mk = maskRow[idx];
            s.x = mk.x ? NEG_INF_F : df.x * s.x * SCALE;
            s.y = mk.y ? NEG_INF_F : df.y * s.y * SCALE;
            s.z = mk.z ? NEG_INF_F : df.z * s.z * SCALE;
            s.w = mk.w ? NEG_INF_F : df.w * s.w * SCALE;
            sv[i] = s;
            m = fmaxf(m, fmaxf(fmaxf(s.x, s.y), fmaxf(s.z, s.w)));
        }
        #pragma unroll
        for (int o = 16; o > 0; o >>= 1)
            m = fmaxf(m, __shfl_xor_sync(0xffffffffu, m, o));

        float sum = 0.f;
        #pragma unroll
        for (int i = 0; i < 16; ++i) {
            float4 s = sv[i];
            s.x = __expf(s.x - m); s.y = __expf(s.y - m);
            s.z = __expf(s.z - m); s.w = __expf(s.w - m);
            sv[i] = s;
            sum += s.x + s.y + s.z + s.w;
        }
        #pragma unroll
        for (int o = 16; o > 0; o >>= 1)
            sum += __shfl_xor_sync(0xffffffffu, sum, o);
        float inv = 1.f / sum;

        #pragma unroll
        for (int i = 0; i < 16; ++i) {
            int idx = i * 32 + lane;
            float4 s = sv[i];
            scRow[idx] = s;
            attnRow[idx] = make_float4(s.x * inv, s.y * inv, s.z * inv, s.w * inv);
        }
        if (lane == 0) invs[q] = inv;
    }
    __syncthreads();

    // ================= Phase 3: context = p @ V (3xTF32 mma, split-k) =================
    {
        float acc[8][4];
        #pragma unroll
        for (int i = 0; i < 8; ++i)
            #pragma unroll
            for (int j = 0; j < 4; ++j) acc[i][j] = 0.f;

        for (int p = 0; p < S / 256; ++p) {
            // V tile transposed: vt[d][k], stride VTP (odd -> conflict-light)
            const float4* Vg = (const float4*)(V + (rowbase + (size_t)p * 256) * D);
            #pragma unroll
            for (int i = 0; i < 8; ++i) {
                int fidx = t + i * NT;
                int kr = fidx >> 4, d4 = fidx & 15;
                float4 v = Vg[fidx];
                float* dst = buf + (d4 * 4) * VTP + kr;
                dst[0]       = v.x;
                dst[VTP]     = v.y;
                dst[2 * VTP] = v.z;
                dst[3 * VTP] = v.w;
            }
            __syncthreads();

            #pragma unroll
            for (int ks = 0; ks < 2; ++ks) {
                const int kk = warp * 2 + ks;          // k-step within chunk
                const int kcol = p * 256 + kk * 8;
                float a0 = sc[gid * SCP       + kcol + tig];
                float a1 = sc[(gid + 8) * SCP + kcol + tig];
                float a2 = sc[gid * SCP       + kcol + tig + 4];
                float a3 = sc[(gid + 8) * SCP + kcol + tig + 4];
                uint32_t Ah[4], Al[4];
                split_tf32(a0, Ah[0], Al[0]);
                split_tf32(a1, Ah[1], Al[1]);
                split_tf32(a2, Ah[2], Al[2]);
                split_tf32(a3, Ah[3], Al[3]);

                const float* vb = buf + gid * VTP + kk * 8 + tig;
                #pragma unroll
                for (int nt = 0; nt < 8; ++nt) {
                    float b0f = vb[nt * 8 * VTP];
                    float b1f = vb[nt * 8 * VTP + 4];
                    uint32_t bh0, bl0, bh1, bl1;
                    split_tf32(b0f, bh0, bl0);
                    split_tf32(b1f, bh1, bl1);
                    mma_tf32(acc[nt], Ah[0], Ah[1], Ah[2], Ah[3], bh0, bh1);
                    mma_tf32(acc[nt], Ah[0], Ah[1], Ah[2], Ah[3], bl0, bl1);
                    mma_tf32(acc[nt], Al[0], Al[1], Al[2], Al[3], bh0, bh1);
                }
            }
            __syncthreads();
        }

        // split-k reduce across 16 warps: red[warp][q][d], q-stride RDP
        float* red = buf;
        #pragma unroll
        for (int nt = 0; nt < 8; ++nt) {
            const int col = nt * 8 + 2 * tig;
            *(float2*)(red + warp * (TQ * RDP) + gid * RDP + col) =
                make_float2(acc[nt][0], acc[nt][1]);
            *(float2*)(red + warp * (TQ * RDP) + (gid + 8) * RDP + col) =
                make_float2(acc[nt][2], acc[nt][3]);
        }
        __syncthreads();

        #pragma unroll
        for (int o = t; o < TQ * D; o += NT) {
            int q = o >> 6, d = o & 63;
            float s = 0.f;
            #pragma unroll
            for (int g = 0; g < 16; ++g)
                s += red[g * (TQ * RDP) + q * RDP + d];
            ctx[(rowbase + q0 + q) * D + d] = s * invs[q];
        }
    }
}

extern "C" void kernel_launch(void* const* d_in, const int* in_sizes, int n_in,
                              void* d_out, int out_size)
{
    const float* Q    = (const float*)d_in[0];
    const float* K    = (const float*)d_in[1];
    const float* V    = (const float*)d_in[2];
    const float* dist = (const float*)d_in[3];
    const int*   mask = (const int*)d_in[4];

    float* ctx  = (float*)d_out;
    float* attn = (float*)d_out + (size_t)BH * S * D;

    cudaFuncSetAttribute(dist_attn_kernel,
                         cudaFuncAttributeMaxDynamicSharedMemorySize,
                         SMEM_BYTES);

    dim3 grid(S / TQ, BH);
    dist_attn_kernel<<<grid, NT, SMEM_BYTES>>>(Q, K, V, dist, mask, ctx, attn);
}

// round 6
// speedup vs baseline: 2.7495x; 1.1396x over previous
#include <cuda_runtime.h>
#include <cstdint>

#define BH   32
#define S    2048
#define D    64
#define TQ   16
#define NT   512
#define SCP  2052            // score row stride (floats)
#define KVP  68              // K/V tile row stride
#define QSP  68
#define TILE_R 128
#define NTILES (S / TILE_R)          // 16
#define TILE_FLOATS (TILE_R * KVP)   // 8704
#define NEG_INF_F (-1e10f)
#define SCALE     (0.125f)

#define SC_FLOATS  (TQ * SCP)        // 32832
#define SMEM_FLOATS (SC_FLOATS + 2 * TILE_FLOATS + TQ * QSP + 32)
#define SMEM_BYTES  (SMEM_FLOATS * 4)

__device__ __forceinline__ void split_tf32(float a, uint32_t& hi, uint32_t& lo) {
    uint32_t h;
    asm("cvt.rna.tf32.f32 %0, %1;" : "=r"(h) : "f"(a));
    hi = h;
    lo = __float_as_uint(a - __uint_as_float(h));
}

__device__ __forceinline__ void mma_tf32(float* c,
                                         uint32_t a0, uint32_t a1, uint32_t a2, uint32_t a3,
                                         uint32_t b0, uint32_t b1) {
    asm volatile(
        "mma.sync.aligned.m16n8k8.row.col.f32.tf32.tf32.f32 "
        "{%0,%1,%2,%3},{%4,%5,%6,%7},{%8,%9},{%0,%1,%2,%3};"
        : "+f"(c[0]), "+f"(c[1]), "+f"(c[2]), "+f"(c[3])
        : "r"(a0), "r"(a1), "r"(a2), "r"(a3), "r"(b0), "r"(b1));
}

// async-copy one 128x64 fp32 tile (gsrc in float4 units) into padded smem buf
__device__ __forceinline__ void cp_tile(const float4* gsrc, float* buf, int t) {
    #pragma unroll
    for (int i = 0; i < 4; ++i) {
        int fidx = t + i * NT;
        int kr = fidx >> 4, d4 = fidx & 15;
        uint32_t sm = (uint32_t)__cvta_generic_to_shared(buf + kr * KVP + d4 * 4);
        asm volatile("cp.async.cg.shared.global [%0], [%1], 16;" :: "r"(sm), "l"(gsrc + fidx));
    }
    asm volatile("cp.async.commit_group;");
}

__device__ __forceinline__ void cp_wait_all() {
    asm volatile("cp.async.wait_group 0;" ::: "memory");
}

__global__ __launch_bounds__(NT, 1)
void dist_attn_kernel(const float* __restrict__ Q,
                      const float* __restrict__ K,
                      const float* __restrict__ V,
                      const float* __restrict__ dist,
                      const int* __restrict__ mask,
                      float* __restrict__ ctx,
                      float* __restrict__ attn)
{
    extern __shared__ float sm[];
    float* sc   = sm;                        // [TQ][SCP]
    float* bufA = sm + SC_FLOATS;            // tile buffer 0
    float* bufB = bufA + TILE_FLOATS;        // tile buffer 1
    float* Qs   = bufB + TILE_FLOATS;        // [TQ][QSP]
    float* invs = Qs + TQ * QSP;             // [TQ]

    const int t    = threadIdx.x;
    const int warp = t >> 5;
    const int lane = t & 31;
    const int gid  = lane >> 2;
    const int tig  = lane & 3;
    const int bh = blockIdx.y;
    const int q0 = blockIdx.x * TQ;
    const size_t rowbase = (size_t)bh * S;

    const float4* Kg4 = (const float4*)(K + rowbase * D);
    const float4* Vg4 = (const float4*)(V + rowbase * D);

    // kick off K tile 0 immediately
    cp_tile(Kg4, bufA, t);

    // Q tile: 16x64, padded stride
    if (t < 256) {
        const float4 v = ((const float4*)(Q + (rowbase + q0) * D))[t];
        int qr = t >> 4, d4 = t & 15;
        *(float4*)(Qs + qr * QSP + d4 * 4) = v;
    }
    __syncthreads();

    // persistent Q A-fragments (hi/lo) — 8 k-steps
    uint32_t qhi[8][4], qlo[8][4];
    #pragma unroll
    for (int ks = 0; ks < 8; ++ks) {
        float a0 = Qs[gid * QSP       + ks * 8 + tig];
        float a1 = Qs[(gid + 8) * QSP + ks * 8 + tig];
        float a2 = Qs[gid * QSP       + ks * 8 + tig + 4];
        float a3 = Qs[(gid + 8) * QSP + ks * 8 + tig + 4];
        split_tf32(a0, qhi[ks][0], qlo[ks][0]);
        split_tf32(a1, qhi[ks][1], qlo[ks][1]);
        split_tf32(a2, qhi[ks][2], qlo[ks][2]);
        split_tf32(a3, qhi[ks][3], qlo[ks][3]);
    }

    // ================= Phase 1: scores = Q @ K^T =================
    // warp w owns 8 score columns per 128-row tile (n = local K rows w*8..w*8+7)
    for (int p = 0; p < NTILES; ++p) {
        float* cur = (p & 1) ? bufB : bufA;
        float* nxt = (p & 1) ? bufA : bufB;
        cp_wait_all();
        __syncthreads();
        if (p < NTILES - 1) cp_tile(Kg4 + (p + 1) * (TILE_R * D / 4), nxt, t);

        float aHH[4] = {0,0,0,0}, aHL[4] = {0,0,0,0}, aLH[4] = {0,0,0,0};
        const float* kb = cur + (warp * 8 + gid) * KVP + tig;
        #pragma unroll
        for (int ks = 0; ks < 8; ++ks) {
            float b0f = kb[ks * 8];
            float b1f = kb[ks * 8 + 4];
            uint32_t bh0, bl0, bh1, bl1;
            split_tf32(b0f, bh0, bl0);
            split_tf32(b1f, bh1, bl1);
            mma_tf32(aHH, qhi[ks][0], qhi[ks][1], qhi[ks][2], qhi[ks][3], bh0, bh1);
            mma_tf32(aHL, qhi[ks][0], qhi[ks][1], qhi[ks][2], qhi[ks][3], bl0, bl1);
            mma_tf32(aLH, qlo[ks][0], qlo[ks][1], qlo[ks][2], qlo[ks][3], bh0, bh1);
        }
        const int col = p * TILE_R + warp * 8 + 2 * tig;
        *(float2*)(sc + gid * SCP + col) =
            make_float2(aHH[0] + aHL[0] + aLH[0], aHH[1] + aHL[1] + aLH[1]);
        *(float2*)(sc + (gid + 8) * SCP + col) =
            make_float2(aHH[2] + aHL[2] + aLH[2], aHH[3] + aHL[3] + aLH[3]);
    }
    __syncthreads();

    // prefetch V tile 0 (overlaps entire softmax phase)
    cp_tile(Vg4, bufA, t);

    // ================= Phase 2: scale, mask, softmax (warp = row) =================
    {
        const int q = warp;
        const size_t grow = rowbase + q0 + q;
        const float4* distRow = (const float4*)(dist + grow * S);
        const int4*   maskRow = (const int4*)(mask + grow * S);
        float4* scRow   = (float4*)(sc + q * SCP);
        float4* attnRow = (float4*)(attn + grow * S);

        float4 sv[16];
        float m = -3.4e38f;
        #pragma unroll
        for (int i = 0; i < 16; ++i) {
            int idx = i * 32 + lane;
            float4 s  = scRow[idx];
            float4 df = distRow[idx];
            int4   mk = maskRow[idx];
            s.x = mk.x ? NEG_INF_F : df.x * s.x * SCALE;
            s.y = mk.y ? NEG_INF_F : df.y * s.y * SCALE;
            s.z = mk.z ? NEG_INF_F : df.z * s.z * SCALE;
            s.w = mk.w ? NEG_INF_F : df.w * s.w * SCALE;
            sv[i] = s;
            m = fmaxf(m, fmaxf(fmaxf(s.x, s.y), fmaxf(s.z, s.w)));
        }
        #pragma unroll
        for (int o = 16; o > 0; o >>= 1)
            m = fmaxf(m, __shfl_xor_sync(0xffffffffu, m, o));

        float sum = 0.f;
        #pragma unroll
        for (int i = 0; i < 16; ++i) {
            float4 s = sv[i];
            s.x = __expf(s.x - m); s.y = __expf(s.y - m);
            s.z = __expf(s.z - m); s.w = __expf(s.w - m);
            sv[i] = s;
            sum += s.x + s.y + s.z + s.w;
        }
        #pragma unroll
        for (int o = 16; o > 0; o >>= 1)
            sum += __shfl_xor_sync(0xffffffffu, sum, o);
        float inv = 1.f / sum;

        #pragma unroll
        for (int i = 0; i < 16; ++i) {
            int idx = i * 32 + lane;
            float4 s = sv[i];
            scRow[idx] = s;
            attnRow[idx] = make_float4(s.x * inv, s.y * inv, s.z * inv, s.w * inv);
        }
        if (lane == 0) invs[q] = inv;
    }
    __syncthreads();

    // ================= Phase 3: context = p @ V (16-way split-k over warps) =================
    {
        float acc[8][4];
        #pragma unroll
        for (int i = 0; i < 8; ++i)
            #pragma unroll
            for (int j = 0; j < 4; ++j) acc[i][j] = 0.f;

        for (int p = 0; p < NTILES; ++p) {
            float* cur = (p & 1) ? bufB : bufA;
            float* nxt = (p & 1) ? bufA : bufB;
            cp_wait_all();
            __syncthreads();
            if (p < NTILES - 1) cp_tile(Vg4 + (p + 1) * (TILE_R * D / 4), nxt, t);

            // warp w consumes k-rows [w*8, w*8+8) of this tile
            const int kcol = p * TILE_R + warp * 8;
            float a0 = sc[gid * SCP       + kcol + tig];
            float a1 = sc[(gid + 8) * SCP + kcol + tig];
            float a2 = sc[gid * SCP       + kcol + tig + 4];
            float a3 = sc[(gid + 8) * SCP + kcol + tig + 4];
            uint32_t Ah[4], Al[4];
            split_tf32(a0, Ah[0], Al[0]);
            split_tf32(a1, Ah[1], Al[1]);
            split_tf32(a2, Ah[2], Al[2]);
            split_tf32(a3, Ah[3], Al[3]);

            const float* vb = cur + (warp * 8 + tig) * KVP + gid;
            #pragma unroll
            for (int nt = 0; nt < 8; ++nt) {
                float b0f = vb[nt * 8];
                float b1f = vb[4 * KVP + nt * 8];
                uint32_t bh0, bl0, bh1, bl1;
                split_tf32(b0f, bh0, bl0);
                split_tf32(b1f, bh1, bl1);
                mma_tf32(acc[nt], Ah[0], Ah[1], Ah[2], Ah[3], bh0, bh1);
                mma_tf32(acc[nt], Ah[0], Ah[1], Ah[2], Ah[3], bl0, bl1);
                mma_tf32(acc[nt], Al[0], Al[1], Al[2], Al[3], bh0, bh1);
            }
        }
        __syncthreads();

        // split-k reduce: red[warp][q][d] (spans bufA+bufB)
        float* red = bufA;
        #pragma unroll
        for (int nt = 0; nt < 8; ++nt) {
            const int col = nt * 8 + 2 * tig;
            *(float2*)(red + warp * (TQ * KVP) + gid * KVP + col) =
                make_float2(acc[nt][0], acc[nt][1]);
            *(float2*)(red + warp * (TQ * KVP) + (gid + 8) * KVP + col) =
                make_float2(acc[nt][2], acc[nt][3]);
        }
        __syncthreads();

        #pragma unroll
        for (int o = t; o < TQ * D; o += NT) {
            int q = o >> 6, d = o & 63;
            float s = 0.f;
            #pragma unroll
            for (int g = 0; g < 16; ++g)
                s += red[g * (TQ * KVP) + q * KVP + d];
            ctx[(rowbase + q0 + q) * D + d] = s * invs[q];
        }
    }
}

extern "C" void kernel_launch(void* const* d_in, const int* in_sizes, int n_in,
                              void* d_out, int out_size)
{
    const float* Q    = (const float*)d_in[0];
    const float* K    = (const float*)d_in[1];
    const float* V    = (const float*)d_in[2];
    const float* dist = (const float*)d_in[3];
    const int*   mask = (const int*)d_in[4];

    float* ctx  = (float*)d_out;
    float* attn = (float*)d_out + (size_t)BH * S * D;

    cudaFuncSetAttribute(dist_attn_kernel,
                         cudaFuncAttributeMaxDynamicSharedMemorySize,
                         SMEM_BYTES);

    dim3 grid(S / TQ, BH);
    dist_attn_kernel<<<grid, NT, SMEM_BYTES>>>(Q, K, V, dist, mask, ctx, attn);
}

// round 7
// speedup vs baseline: 3.0449x; 1.1074x over previous
#include <cuda_runtime.h>
#include <cstdint>

#define BH   32
#define S    2048
#define D    64
#define TQ   16
#define NT   512
#define SCP  2052            // score row stride (floats)
#define KVP  68              // K/V tile row stride
#define QSP  68
#define RMP  18              // rowmax stride
#define TILE_R 128
#define NTILES (S / TILE_R)          // 16
#define TILE_FLOATS (TILE_R * KVP)   // 8704
#define NEG_INF_F (-1e10f)
#define SCALE     (0.125f)

#define SC_FLOATS  (TQ * SCP)        // 32832
#define SMEM_FLOATS (SC_FLOATS + 2 * TILE_FLOATS + TQ * QSP + 16 * RMP + TQ + 32)
#define SMEM_BYTES  (SMEM_FLOATS * 4)

// exact 2-term split via mantissa truncation (ALU LOP3, not F2FP)
__device__ __forceinline__ void split_tf32(float a, uint32_t& hi, uint32_t& lo) {
    uint32_t h = __float_as_uint(a) & 0xFFFFE000u;
    hi = h;
    lo = __float_as_uint(a - __uint_as_float(h));
}

__device__ __forceinline__ void mma_tf32(float* c,
                                         uint32_t a0, uint32_t a1, uint32_t a2, uint32_t a3,
                                         uint32_t b0, uint32_t b1) {
    asm volatile(
        "mma.sync.aligned.m16n8k8.row.col.f32.tf32.tf32.f32 "
        "{%0,%1,%2,%3},{%4,%5,%6,%7},{%8,%9},{%0,%1,%2,%3};"
        : "+f"(c[0]), "+f"(c[1]), "+f"(c[2]), "+f"(c[3])
        : "r"(a0), "r"(a1), "r"(a2), "r"(a3), "r"(b0), "r"(b1));
}

__device__ __forceinline__ void cp_tile(const float4* gsrc, float* buf, int t) {
    #pragma unroll
    for (int i = 0; i < 4; ++i) {
        int fidx = t + i * NT;
        int kr = fidx >> 4, d4 = fidx & 15;
        uint32_t sm = (uint32_t)__cvta_generic_to_shared(buf + kr * KVP + d4 * 4);
        asm volatile("cp.async.cg.shared.global [%0], [%1], 16;" :: "r"(sm), "l"(gsrc + fidx));
    }
    asm volatile("cp.async.commit_group;");
}

__device__ __forceinline__ void cp_wait_all() {
    asm volatile("cp.async.wait_group 0;" ::: "memory");
}

__global__ __launch_bounds__(NT, 1)
void dist_attn_kernel(const float* __restrict__ Q,
                      const float* __restrict__ K,
                      const float* __restrict__ V,
                      const float* __restrict__ dist,
                      const int* __restrict__ mask,
                      float* __restrict__ ctx,
                      float* __restrict__ attn)
{
    extern __shared__ float sm[];
    float* sc     = sm;                       // [TQ][SCP] masked scaled scores -> probs
    float* bufA   = sm + SC_FLOATS;
    float* bufB   = bufA + TILE_FLOATS;
    float* Qs     = bufB + TILE_FLOATS;       // [TQ][QSP]
    float* rowmax = Qs + TQ * QSP;            // [16 warps][RMP]
    float* invs   = rowmax + 16 * RMP;        // [TQ]

    const int t    = threadIdx.x;
    const int warp = t >> 5;
    const int lane = t & 31;
    const int gid  = lane >> 2;
    const int tig  = lane & 3;
    const int bh = blockIdx.y;
    const int q0 = blockIdx.x * TQ;
    const size_t rowbase = (size_t)bh * S;

    const float4* Kg4 = (const float4*)(K + rowbase * D);
    const float4* Vg4 = (const float4*)(V + rowbase * D);

    cp_tile(Kg4, bufA, t);

    if (t < 256) {
        const float4 v = ((const float4*)(Q + (rowbase + q0) * D))[t];
        int qr = t >> 4, d4 = t & 15;
        *(float4*)(Qs + qr * QSP + d4 * 4) = v;
    }
    __syncthreads();

    // persistent Q A-fragments (hi/lo), 8 k-steps
    uint32_t qhi[8][4], qlo[8][4];
    #pragma unroll
    for (int ks = 0; ks < 8; ++ks) {
        float a0 = Qs[gid * QSP       + ks * 8 + tig];
        float a1 = Qs[(gid + 8) * QSP + ks * 8 + tig];
        float a2 = Qs[gid * QSP       + ks * 8 + tig + 4];
        float a3 = Qs[(gid + 8) * QSP + ks * 8 + tig + 4];
        split_tf32(a0, qhi[ks][0], qlo[ks][0]);
        split_tf32(a1, qhi[ks][1], qlo[ks][1]);
        split_tf32(a2, qhi[ks][2], qlo[ks][2]);
        split_tf32(a3, qhi[ks][3], qlo[ks][3]);
    }

    // ============ Phase 1: scores = Q@K^T fused with dist/mask/scale + row-max ============
    const size_t row0g = rowbase + q0 + gid;       // global row of gid
    float m0 = -3.4e38f, m1 = -3.4e38f;            // running max for rows gid, gid+8

    for (int p = 0; p < NTILES; ++p) {
        float* cur = (p & 1) ? bufB : bufA;
        float* nxt = (p & 1) ? bufA : bufB;
        cp_wait_all();
        __syncthreads();
        if (p < NTILES - 1) cp_tile(Kg4 + (p + 1) * (TILE_R * D / 4), nxt, t);

        const int col = p * TILE_R + warp * 8 + 2 * tig;
        // issue dist/mask loads early (independent of MMAs)
        float2 d0 = *(const float2*)(dist + row0g * S + col);
        float2 d1 = *(const float2*)(dist + (row0g + 8) * S + col);
        int2   k0 = *(const int2*)(mask + row0g * S + col);
        int2   k1 = *(const int2*)(mask + (row0g + 8) * S + col);

        float aHH[4] = {0,0,0,0}, aHL[4] = {0,0,0,0}, aLH[4] = {0,0,0,0};
        const float* kb = cur + (warp * 8 + gid) * KVP + tig;
        #pragma unroll
        for (int ks = 0; ks < 8; ++ks) {
            float b0f = kb[ks * 8];
            float b1f = kb[ks * 8 + 4];
            uint32_t bh0, bl0, bh1, bl1;
            split_tf32(b0f, bh0, bl0);
            split_tf32(b1f, bh1, bl1);
            mma_tf32(aHH, qhi[ks][0], qhi[ks][1], qhi[ks][2], qhi[ks][3], bh0, bh1);
            mma_tf32(aHL, qhi[ks][0], qhi[ks][1], qhi[ks][2], qhi[ks][3], bl0, bl1);
            mma_tf32(aLH, qlo[ks][0], qlo[ks][1], qlo[ks][2], qlo[ks][3], bh0, bh1);
        }
        float s0 = aHH[0] + aHL[0] + aLH[0];
        float s1 = aHH[1] + aHL[1] + aLH[1];
        float s2 = aHH[2] + aHL[2] + aLH[2];
        float s3 = aHH[3] + aHL[3] + aLH[3];
        s0 = k0.x ? NEG_INF_F : d0.x * s0 * SCALE;
        s1 = k0.y ? NEG_INF_F : d0.y * s1 * SCALE;
        s2 = k1.x ? NEG_INF_F : d1.x * s2 * SCALE;
        s3 = k1.y ? NEG_INF_F : d1.y * s3 * SCALE;
        m0 = fmaxf(m0, fmaxf(s0, s1));
        m1 = fmaxf(m1, fmaxf(s2, s3));
        *(float2*)(sc + gid * SCP + col)       = make_float2(s0, s1);
        *(float2*)(sc + (gid + 8) * SCP + col) = make_float2(s2, s3);
    }
    // reduce max over tig (lanes gid*4 + tig)
    #pragma unroll
    for (int o = 1; o <= 2; o <<= 1) {
        m0 = fmaxf(m0, __shfl_xor_sync(0xffffffffu, m0, o));
        m1 = fmaxf(m1, __shfl_xor_sync(0xffffffffu, m1, o));
    }
    if (tig == 0) {
        rowmax[warp * RMP + gid]     = m0;
        rowmax[warp * RMP + gid + 8] = m1;
    }
    __syncthreads();

    // prefetch V tile 0 (overlaps softmax)
    cp_tile(Vg4, bufA, t);

    // ============ Phase 2: exp + sum + attn write (warp = row) ============
    {
        const int q = warp;
        const size_t grow = rowbase + q0 + q;
        float4* scRow   = (float4*)(sc + q * SCP);
        float4* attnRow = (float4*)(attn + grow * S);

        float m = (lane < 16) ? rowmax[lane * RMP + q] : -3.4e38f;
        #pragma unroll
        for (int o = 16; o > 0; o >>= 1)
            m = fmaxf(m, __shfl_xor_sync(0xffffffffu, m, o));

        float4 sv[16];
        float sum = 0.f;
        #pragma unroll
        for (int i = 0; i < 16; ++i) {
            float4 s = scRow[i * 32 + lane];
            s.x = __expf(s.x - m); s.y = __expf(s.y - m);
            s.z = __expf(s.z - m); s.w = __expf(s.w - m);
            sv[i] = s;
            sum += s.x + s.y + s.z + s.w;
        }
        #pragma unroll
        for (int o = 16; o > 0; o >>= 1)
            sum += __shfl_xor_sync(0xffffffffu, sum, o);
        float inv = 1.f / sum;

        #pragma unroll
        for (int i = 0; i < 16; ++i) {
            int idx = i * 32 + lane;
            float4 s = sv[i];
            scRow[idx] = s;                                      // unnormalized p
            attnRow[idx] = make_float4(s.x * inv, s.y * inv, s.z * inv, s.w * inv);
        }
        if (lane == 0) invs[q] = inv;
    }
    __syncthreads();

    // ============ Phase 3: context = p @ V (16-way split-k over warps) ============
    {
        float acc[8][4];
        #pragma unroll
        for (int i = 0; i < 8; ++i)
            #pragma unroll
            for (int j = 0; j < 4; ++j) acc[i][j] = 0.f;

        for (int p = 0; p < NTILES; ++p) {
            float* cur = (p & 1) ? bufB : bufA;
            float* nxt = (p & 1) ? bufA : bufB;
            cp_wait_all();
            __syncthreads();
            if (p < NTILES - 1) cp_tile(Vg4 + (p + 1) * (TILE_R * D / 4), nxt, t);

            const int kcol = p * TILE_R + warp * 8;
            float a0 = sc[gid * SCP       + kcol + tig];
            float a1 = sc[(gid + 8) * SCP + kcol + tig];
            float a2 = sc[gid * SCP       + kcol + tig + 4];
            float a3 = sc[(gid + 8) * SCP + kcol + tig + 4];
            uint32_t Ah[4], Al[4];
            split_tf32(a0, Ah[0], Al[0]);
            split_tf32(a1, Ah[1], Al[1]);
            split_tf32(a2, Ah[2], Al[2]);
            split_tf32(a3, Ah[3], Al[3]);

            const float* vb = cur + (warp * 8 + tig) * KVP + gid;
            #pragma unroll
            for (int nt = 0; nt < 8; ++nt) {
                float b0f = vb[nt * 8];
                float b1f = vb[4 * KVP + nt * 8];
                uint32_t bh0, bl0, bh1, bl1;
                split_tf32(b0f, bh0, bl0);
                split_tf32(b1f, bh1, bl1);
                mma_tf32(acc[nt], Ah[0], Ah[1], Ah[2], Ah[3], bh0, bh1);
                mma_tf32(acc[nt], Ah[0], Ah[1], Ah[2], Ah[3], bl0, bl1);
                mma_tf32(acc[nt], Al[0], Al[1], Al[2], Al[3], bh0, bh1);
            }
        }
        __syncthreads();

        // split-k reduce: red[warp][q][d]
        float* red = bufA;
        #pragma unroll
        for (int nt = 0; nt < 8; ++nt) {
            const int col = nt * 8 + 2 * tig;
            *(float2*)(red + warp * (TQ * KVP) + gid * KVP + col) =
                make_float2(acc[nt][0], acc[nt][1]);
            *(float2*)(red + warp * (TQ * KVP) + (gid + 8) * KVP + col) =
                make_float2(acc[nt][2], acc[nt][3]);
        }
        __syncthreads();

        #pragma unroll
        for (int o = t; o < TQ * D; o += NT) {
            int q = o >> 6, d = o & 63;
            float s = 0.f;
            #pragma unroll
            for (int g = 0; g < 16; ++g)
                s += red[g * (TQ * KVP) + q * KVP + d];
            ctx[(rowbase + q0 + q) * D + d] = s * invs[q];
        }
    }
}

extern "C" void kernel_launch(void* const* d_in, const int* in_sizes, int n_in,
                              void* d_out, int out_size)
{
    const float* Q    = (const float*)d_in[0];
    const float* K    = (const float*)d_in[1];
    const float* V    = (const float*)d_in[2];
    const float* dist = (const float*)d_in[3];
    const int*   mask = (const int*)d_in[4];

    float* ctx  = (float*)d_out;
    float* attn = (float*)d_out + (size_t)BH * S * D;

    cudaFuncSetAttribute(dist_attn_kernel,
                         cudaFuncAttributeMaxDynamicSharedMemorySize,
                         SMEM_BYTES);

    dim3 grid(S / TQ, BH);
    dist_attn_kernel<<<grid, NT, SMEM_BYTES>>>(Q, K, V, dist, mask, ctx, attn);
}